// round 13
// baseline (speedup 1.0000x reference)
#include <cuda_runtime.h>
#include <math.h>

// Problem constants (B=64, S=256, D=1024 per reference setup_inputs)
#define DIM   1024
#define SEQ   256
#define BATCH 64
#define MTOT  (BATCH * SEQ)   // 16384 rows

// ---------------------------------------------------------------------------
// Scratch (device globals: allocation-free per harness rules)
// ---------------------------------------------------------------------------
__device__ float g_t0[(size_t)MTOT * DIM];      // adain_input (content)
__device__ float g_xn[(size_t)MTOT * DIM];      // layernorm output
__device__ float g_scale[BATCH * DIM];          // adain: s_std / c_std
__device__ float g_shift[BATCH * DIM];          // adain: s_mean - c_mean*scale

__device__ __forceinline__ float silu_f(float v) {
    return v / (1.f + __expf(-v));
}

// ---------------------------------------------------------------------------
// NT SGEMM: C[m,n] = sum_k A[m,k] * B[n,k]   (A: [M,K] rm, B: [N,K] rm)
// Tile 128x128x8, 256 threads, 8x8 per thread. N is always DIM (=1024).
// EPI 0: C = acc + bias[n]                            (write g_t0)
// EPI 2: C = acc + bias[n] + T0*scale + shift         (adain fuse, write x)
// EPI 3: C += silu(acc + bias[n])                     (residual, in-place x)
// SILU_A: apply silu to A elements while loading (for silu(embed)).
// ---------------------------------------------------------------------------
template<int EPI, bool SILU_A>
__global__ __launch_bounds__(256, 2) void gemm_nt_k(
    const float* __restrict__ A, const float* __restrict__ B,
    const float* __restrict__ bias,
    const float* __restrict__ T0, const float* __restrict__ SC,
    const float* __restrict__ SH,
    float* __restrict__ C, int K)
{
    __shared__ __align__(16) float As[8][128];
    __shared__ __align__(16) float Bs[8][128];

    const int tid = threadIdx.x;
    const int tx  = tid & 15;       // 0..15  -> 8 output cols each
    const int ty  = tid >> 4;       // 0..15  -> 8 output rows each
    const int m0  = blockIdx.y << 7;
    const int n0  = blockIdx.x << 7;

    const int lrow = tid >> 1;          // 0..127
    const int lk   = (tid & 1) << 2;    // 0 or 4

    const float* Ald = A + (size_t)(m0 + lrow) * K + lk;
    const float* Bld = B + (size_t)(n0 + lrow) * K + lk;

    float acc[8][8];
#pragma unroll
    for (int i = 0; i < 8; i++)
#pragma unroll
        for (int j = 0; j < 8; j++) acc[i][j] = 0.f;

    for (int k0 = 0; k0 < K; k0 += 8) {
        float4 av = *reinterpret_cast<const float4*>(Ald + k0);
        if (SILU_A) {
            av.x = silu_f(av.x); av.y = silu_f(av.y);
            av.z = silu_f(av.z); av.w = silu_f(av.w);
        }
        float4 bv = *reinterpret_cast<const float4*>(Bld + k0);
        As[lk + 0][lrow] = av.x; As[lk + 1][lrow] = av.y;
        As[lk + 2][lrow] = av.z; As[lk + 3][lrow] = av.w;
        Bs[lk + 0][lrow] = bv.x; Bs[lk + 1][lrow] = bv.y;
        Bs[lk + 2][lrow] = bv.z; Bs[lk + 3][lrow] = bv.w;
        __syncthreads();

#pragma unroll
        for (int kk = 0; kk < 8; kk++) {
            float4 a0 = *reinterpret_cast<const float4*>(&As[kk][ty << 3]);
            float4 a1 = *reinterpret_cast<const float4*>(&As[kk][(ty << 3) + 4]);
            float4 b0 = *reinterpret_cast<const float4*>(&Bs[kk][tx << 3]);
            float4 b1 = *reinterpret_cast<const float4*>(&Bs[kk][(tx << 3) + 4]);
            float a[8] = {a0.x, a0.y, a0.z, a0.w, a1.x, a1.y, a1.z, a1.w};
            float b[8] = {b0.x, b0.y, b0.z, b0.w, b1.x, b1.y, b1.z, b1.w};
#pragma unroll
            for (int i = 0; i < 8; i++)
#pragma unroll
                for (int j = 0; j < 8; j++)
                    acc[i][j] = fmaf(a[i], b[j], acc[i][j]);
        }
        __syncthreads();
    }

    // Epilogue (output row stride = DIM)
#pragma unroll
    for (int i = 0; i < 8; i++) {
        const int m = m0 + (ty << 3) + i;
        const size_t ro = (size_t)m * DIM;
#pragma unroll
        for (int q = 0; q < 2; q++) {
            const int n = n0 + (tx << 3) + (q << 2);
            float4 r = make_float4(acc[i][q * 4 + 0], acc[i][q * 4 + 1],
                                   acc[i][q * 4 + 2], acc[i][q * 4 + 3]);
            const float4 bs = *reinterpret_cast<const float4*>(&bias[n]);
            r.x += bs.x; r.y += bs.y; r.z += bs.z; r.w += bs.w;
            if (EPI == 0) {
                *reinterpret_cast<float4*>(&C[ro + n]) = r;
            } else if (EPI == 2) {
                const int bidx = (m >> 8) * DIM + n;   // batch = m / SEQ
                const float4 t0v = *reinterpret_cast<const float4*>(&T0[ro + n]);
                const float4 scv = *reinterpret_cast<const float4*>(&SC[bidx]);
                const float4 shv = *reinterpret_cast<const float4*>(&SH[bidx]);
                r.x += fmaf(t0v.x, scv.x, shv.x);
                r.y += fmaf(t0v.y, scv.y, shv.y);
                r.z += fmaf(t0v.z, scv.z, shv.z);
                r.w += fmaf(t0v.w, scv.w, shv.w);
                *reinterpret_cast<float4*>(&C[ro + n]) = r;
            } else { // EPI == 3
                float4 xv = *reinterpret_cast<const float4*>(&C[ro + n]);
                xv.x += silu_f(r.x); xv.y += silu_f(r.y);
                xv.z += silu_f(r.z); xv.w += silu_f(r.w);
                *reinterpret_cast<float4*>(&C[ro + n]) = xv;
            }
        }
    }
}

// ---------------------------------------------------------------------------
// Batched NN GEMM for block 0 (1x1 Conv1d over seq axis):
//   out[b,t,d] = sum_s W0[t,s] * XN[b,s,d];  X[b,t,d] += silu(out + b0[t])
// Grid: (DIM/128, SEQ/128, BATCH)
// ---------------------------------------------------------------------------
__global__ __launch_bounds__(256, 2) void gemm_nn_block0_k(
    const float* __restrict__ W0, const float* __restrict__ b0,
    const float* __restrict__ XN, float* __restrict__ X)
{
    __shared__ __align__(16) float As[8][128];
    __shared__ __align__(16) float Bs[8][128];

    const int tid = threadIdx.x;
    const int tx  = tid & 15;
    const int ty  = tid >> 4;
    const int b   = blockIdx.z;
    const int m0  = blockIdx.y << 7;   // t offset
    const int n0  = blockIdx.x << 7;   // d offset
    const float* Bsrc = XN + (size_t)b * SEQ * DIM;

    const int arow = tid >> 1, ak = (tid & 1) << 2;   // A: 128 rows x 8 k
    const int brow = tid >> 5, bcol = (tid & 31) << 2; // B: 8 rows x 128 cols

    float acc[8][8];
#pragma unroll
    for (int i = 0; i < 8; i++)
#pragma unroll
        for (int j = 0; j < 8; j++) acc[i][j] = 0.f;

    for (int k0 = 0; k0 < SEQ; k0 += 8) {
        float4 av = *reinterpret_cast<const float4*>(
            &W0[(size_t)(m0 + arow) * SEQ + k0 + ak]);
        As[ak + 0][arow] = av.x; As[ak + 1][arow] = av.y;
        As[ak + 2][arow] = av.z; As[ak + 3][arow] = av.w;
        float4 bv = *reinterpret_cast<const float4*>(
            &Bsrc[(size_t)(k0 + brow) * DIM + n0 + bcol]);
        *reinterpret_cast<float4*>(&Bs[brow][bcol]) = bv;
        __syncthreads();

#pragma unroll
        for (int kk = 0; kk < 8; kk++) {
            float4 a0 = *reinterpret_cast<const float4*>(&As[kk][ty << 3]);
            float4 a1 = *reinterpret_cast<const float4*>(&As[kk][(ty << 3) + 4]);
            float4 b0v = *reinterpret_cast<const float4*>(&Bs[kk][tx << 3]);
            float4 b1v = *reinterpret_cast<const float4*>(&Bs[kk][(tx << 3) + 4]);
            float a[8] = {a0.x, a0.y, a0.z, a0.w, a1.x, a1.y, a1.z, a1.w};
            float bb[8] = {b0v.x, b0v.y, b0v.z, b0v.w, b1v.x, b1v.y, b1v.z, b1v.w};
#pragma unroll
            for (int i = 0; i < 8; i++)
#pragma unroll
                for (int j = 0; j < 8; j++)
                    acc[i][j] = fmaf(a[i], bb[j], acc[i][j]);
        }
        __syncthreads();
    }

#pragma unroll
    for (int i = 0; i < 8; i++) {
        const int t = m0 + (ty << 3) + i;
        const float biasr = b0[t];
        const size_t ro = ((size_t)b * SEQ + t) * DIM;
#pragma unroll
        for (int q = 0; q < 2; q++) {
            const int n = n0 + (tx << 3) + (q << 2);
            float4 xv = *reinterpret_cast<const float4*>(&X[ro + n]);
            xv.x += silu_f(acc[i][q * 4 + 0] + biasr);
            xv.y += silu_f(acc[i][q * 4 + 1] + biasr);
            xv.z += silu_f(acc[i][q * 4 + 2] + biasr);
            xv.w += silu_f(acc[i][q * 4 + 3] + biasr);
            *reinterpret_cast<float4*>(&X[ro + n]) = xv;
        }
    }
}

// ---------------------------------------------------------------------------
// AdaIN stats: per (b,d) over the seq axis (unbiased var, eps=1e-5).
// scale = s_std/c_std; shift = s_mean - c_mean*scale.
// Grid: (DIM/256, BATCH), 256 threads.
// ---------------------------------------------------------------------------
__global__ __launch_bounds__(256) void adain_stats_k(
    const float* __restrict__ content, const float* __restrict__ style,
    float* __restrict__ scale, float* __restrict__ shift)
{
    const int d = blockIdx.x * 256 + threadIdx.x;
    const int b = blockIdx.y;
    const size_t base = (size_t)b * SEQ * DIM + d;

    float sc = 0.f, scc = 0.f, sm = 0.f, sss = 0.f;
    for (int s = 0; s < SEQ; s++) {
        const float c  = content[base + (size_t)s * DIM];
        const float st = style[base + (size_t)s * DIM];
        sc  = sc + c;   scc = fmaf(c, c, scc);
        sm  = sm + st;  sss = fmaf(st, st, sss);
    }
    const float invS = 1.f / (float)SEQ;
    const float cm = sc * invS;
    const float smn = sm * invS;
    const float cvar = (scc - (float)SEQ * cm * cm) * (1.f / (float)(SEQ - 1));
    const float svar = (sss - (float)SEQ * smn * smn) * (1.f / (float)(SEQ - 1));
    const float cstd = sqrtf(cvar + 1e-5f);
    const float sstd = sqrtf(svar + 1e-5f);
    const float k = sstd / cstd;
    scale[b * DIM + d] = k;
    shift[b * DIM + d] = smn - cm * k;
}

// ---------------------------------------------------------------------------
// LayerNorm over last dim (D=1024), biased var, eps=1e-5, affine g/beta.
// One block (256 threads, float4 per thread) per row.
// ---------------------------------------------------------------------------
__global__ __launch_bounds__(256) void ln_k(
    const float* __restrict__ X, const float* __restrict__ g,
    const float* __restrict__ beta, float* __restrict__ Y)
{
    const int row = blockIdx.x;
    const int tid = threadIdx.x;
    const float4 v = reinterpret_cast<const float4*>(X + (size_t)row * DIM)[tid];

    float s  = v.x + v.y + v.z + v.w;
    float ss = fmaf(v.x, v.x, fmaf(v.y, v.y, fmaf(v.z, v.z, v.w * v.w)));

    __shared__ float sh_s[8], sh_ss[8];
#pragma unroll
    for (int o = 16; o > 0; o >>= 1) {
        s  += __shfl_down_sync(0xffffffffu, s,  o);
        ss += __shfl_down_sync(0xffffffffu, ss, o);
    }
    if ((tid & 31) == 0) { sh_s[tid >> 5] = s; sh_ss[tid >> 5] = ss; }
    __syncthreads();
    if (tid < 32) {
        float a  = (tid < 8) ? sh_s[tid]  : 0.f;
        float a2 = (tid < 8) ? sh_ss[tid] : 0.f;
#pragma unroll
        for (int o = 4; o > 0; o >>= 1) {
            a  += __shfl_down_sync(0xffffffffu, a,  o);
            a2 += __shfl_down_sync(0xffffffffu, a2, o);
        }
        if (tid == 0) { sh_s[0] = a; sh_ss[0] = a2; }
    }
    __syncthreads();

    const float mu  = sh_s[0] * (1.f / (float)DIM);
    const float var = sh_ss[0] * (1.f / (float)DIM) - mu * mu;
    const float inv = rsqrtf(var + 1e-5f);

    const float4 gv = reinterpret_cast<const float4*>(g)[tid];
    const float4 bv = reinterpret_cast<const float4*>(beta)[tid];
    float4 o;
    o.x = (v.x - mu) * inv * gv.x + bv.x;
    o.y = (v.y - mu) * inv * gv.y + bv.y;
    o.z = (v.z - mu) * inv * gv.z + bv.z;
    o.w = (v.w - mu) * inv * gv.w + bv.w;
    reinterpret_cast<float4*>(Y + (size_t)row * DIM)[tid] = o;
}

// ---------------------------------------------------------------------------
// Launch
// ---------------------------------------------------------------------------
extern "C" void kernel_launch(void* const* d_in, const int* in_sizes, int n_in,
                              void* d_out, int out_size)
{
    (void)in_sizes; (void)n_in; (void)out_size;

    const float* x     = (const float*)d_in[0];
    const float* embed = (const float*)d_in[1];
    const float* style = (const float*)d_in[2];
    const float* Wc    = (const float*)d_in[3];
    const float* bc    = (const float*)d_in[4];
    const float* We    = (const float*)d_in[5];
    const float* be    = (const float*)d_in[6];
    const float* W0    = (const float*)d_in[7];
    const float* b0    = (const float*)d_in[8];
    const float* W1    = (const float*)d_in[9];
    const float* b1    = (const float*)d_in[10];
    const float* g0    = (const float*)d_in[11];
    const float* beta0 = (const float*)d_in[12];
    const float* g1    = (const float*)d_in[13];
    const float* beta1 = (const float*)d_in[14];

    float* outx      = (float*)d_out;
    float* out_embed = outx + (size_t)MTOT * DIM;
    float* out_style = out_embed + (size_t)MTOT * DIM;

    float *t0p, *xnp, *scp, *shp;
    cudaGetSymbolAddress((void**)&t0p, g_t0);
    cudaGetSymbolAddress((void**)&xnp, g_xn);
    cudaGetSymbolAddress((void**)&scp, g_scale);
    cudaGetSymbolAddress((void**)&shp, g_shift);

    // 1) adain_input = x @ Wc^T + bc   [16384 x 1024], K = 2048
    gemm_nt_k<0, false><<<dim3(DIM / 128, MTOT / 128), 256>>>(
        x, Wc, bc, nullptr, nullptr, nullptr, t0p, 2 * DIM);

    // 2) AdaIN stats over seq axis -> scale/shift per (b,d)
    adain_stats_k<<<dim3(DIM / 256, BATCH), 256>>>(t0p, style, scp, shp);

    // 3) x = adain(adain_input) + silu(embed) @ We^T + be   (fused epilogue)
    gemm_nt_k<2, true><<<dim3(DIM / 128, MTOT / 128), 256>>>(
        embed, We, be, t0p, scp, shp, outx, DIM);

    // 4) LN0 -> g_xn
    ln_k<<<MTOT, 256>>>(outx, g0, beta0, xnp);

    // 5) x += silu(W0 @ x_ + b0[:,None])   (batched over B, fused epilogue)
    gemm_nn_block0_k<<<dim3(DIM / 128, SEQ / 128, BATCH), 256>>>(W0, b0, xnp, outx);

    // 6) LN1 -> g_xn
    ln_k<<<MTOT, 256>>>(outx, g1, beta1, xnp);

    // 7) x += silu(x_ @ W1^T + b1)   (fused epilogue)
    gemm_nt_k<3, false><<<dim3(DIM / 128, MTOT / 128), 256>>>(
        xnp, W1, b1, nullptr, nullptr, nullptr, outx, DIM);

    // 8) Output tuple tail: copies of embed and style_code
    cudaMemcpyAsync(out_embed, embed, (size_t)MTOT * DIM * sizeof(float),
                    cudaMemcpyDeviceToDevice);
    cudaMemcpyAsync(out_style, style, (size_t)MTOT * DIM * sizeof(float),
                    cudaMemcpyDeviceToDevice);
}